// round 6
// baseline (speedup 1.0000x reference)
#include <cuda_runtime.h>
#include <cstdint>

#define S_LEN 2048
#define D_DIM 1024
#define NH    16
#define HDIM  64
#define NB    2
#define M_TOT 4096

// Scratch. All K-dimensions stored pair-interleaved: within each aligned
// 8-block, new[2k] = old[k], new[2k+1] = old[k+4]  (so fragment pairs (k,k+4)
// are adjacent -> LDS.64 fragment loads). V and all n-dims stay natural.
__device__ float g_q[NB * NH * S_LEN * HDIM];   // [b,h,s,hd~], 0.125-scaled, tf32
__device__ float g_k[NB * NH * S_LEN * HDIM];   // [b,h,s,hd~]
__device__ float g_v[NB * NH * S_LEN * HDIM];   // [b,h,s,hd]  (natural)
__device__ float g_ctx[NB * S_LEN * D_DIM];     // [b,s,d~], tf32
__device__ float g_xc[M_TOT * D_DIM];           // [m,d~], tf32
__device__ float g_wqc[D_DIM * D_DIM];          // [n,d~], tf32
__device__ float g_wkc[D_DIM * D_DIM];
__device__ float g_wvc[D_DIM * D_DIM];
__device__ float g_woc[D_DIM * D_DIM];

// ---------------------------------------------------------------------------
__device__ __forceinline__ uint32_t f2tf(float f) {
    uint32_t u;
    asm("cvt.rna.tf32.f32 %0, %1;" : "=r"(u) : "f"(f));
    return u;
}
__device__ __forceinline__ float u2f(uint32_t u) { return __uint_as_float(u); }
__device__ __forceinline__ uint32_t fbits(float f) { return __float_as_uint(f); }
__device__ __forceinline__ int ilv8(int i) {        // pos within interleaved 8-block
    return (i & ~7) | (((i & 3) << 1) | ((i >> 2) & 1));
}

__device__ __forceinline__ uint32_t smem_u32(const void* p) {
    uint32_t a;
    asm("{ .reg .u64 t; cvta.to.shared.u64 t, %1; cvt.u32.u64 %0, t; }" : "=r"(a) : "l"(p));
    return a;
}
__device__ __forceinline__ void mma_tf32(float d[4], const uint32_t a[4], const uint32_t b[2]) {
    asm("mma.sync.aligned.m16n8k8.row.col.f32.tf32.tf32.f32 "
        "{%0,%1,%2,%3}, {%4,%5,%6,%7}, {%8,%9}, {%0,%1,%2,%3};"
        : "+f"(d[0]), "+f"(d[1]), "+f"(d[2]), "+f"(d[3])
        : "r"(a[0]), "r"(a[1]), "r"(a[2]), "r"(a[3]), "r"(b[0]), "r"(b[1]));
}
__device__ __forceinline__ void cpa16(uint32_t dst, const void* src) {
    asm volatile("cp.async.ca.shared.global [%0], [%1], 16;" :: "r"(dst), "l"(src) : "memory");
}
__device__ __forceinline__ void cpa_commit() {
    asm volatile("cp.async.commit_group;" ::: "memory");
}
template <int N>
__device__ __forceinline__ void cpa_wait() {
    asm volatile("cp.async.wait_group %0;" :: "n"(N) : "memory");
}

// ---------------------------------------------------------------------------
// Prep: tf32-round + pair-interleave K-dim of x and all weights.
// Each 8-float block: out = {i0,i4,i1,i5,i2,i6,i3,i7}.
// ---------------------------------------------------------------------------
__global__ __launch_bounds__(256) void prep_kernel(
    const float* __restrict__ x,  const float* __restrict__ wq,
    const float* __restrict__ wk, const float* __restrict__ wv,
    const float* __restrict__ wo)
{
    const float* src; float* dst; int n8;
    switch (blockIdx.y) {
        case 0: src = x;  dst = g_xc;  n8 = M_TOT * D_DIM / 8; break;
        case 1: src = wq; dst = g_wqc; n8 = D_DIM * D_DIM / 8; break;
        case 2: src = wk; dst = g_wkc; n8 = D_DIM * D_DIM / 8; break;
        case 3: src = wv; dst = g_wvc; n8 = D_DIM * D_DIM / 8; break;
        default: src = wo; dst = g_woc; n8 = D_DIM * D_DIM / 8; break;
    }
    const int stride = gridDim.x * blockDim.x;
    for (int i = blockIdx.x * blockDim.x + threadIdx.x; i < n8; i += stride) {
        float4 lo = __ldg((const float4*)src + 2 * i);
        float4 hi = __ldg((const float4*)src + 2 * i + 1);
        ((float4*)dst)[2 * i] = make_float4(u2f(f2tf(lo.x)), u2f(f2tf(hi.x)),
                                            u2f(f2tf(lo.y)), u2f(f2tf(hi.y)));
        ((float4*)dst)[2 * i + 1] = make_float4(u2f(f2tf(lo.z)), u2f(f2tf(hi.z)),
                                                u2f(f2tf(lo.w)), u2f(f2tf(hi.w)));
    }
}

// ---------------------------------------------------------------------------
// GEMM core: D[128,128] = A[128,1024~] @ B[128,1024~]^T (interleaved k).
// 256 thr, 8 warps 4(m)x2(n); 3-stage cp.async; LDS.64 fragment loads.
// ---------------------------------------------------------------------------
#define GS_A   4608                    // floats per stage (128*36)
#define GB_OFF (3 * GS_A)
#define GEMM_SMEM (6 * GS_A * 4)       // 110592 B

__device__ __forceinline__ void gemm_stage(
    uint32_t sbase, int buf, const float* __restrict__ Ag,
    const float* __restrict__ Bg, int ch)
{
    const int tid = threadIdx.x;
    #pragma unroll
    for (int t = 0; t < 4; t++) {
        int i = tid + t * 256, row = i >> 3, c4 = i & 7;
        cpa16(sbase + (buf * GS_A + row * 36 + c4 * 4) * 4,
              Ag + (size_t)row * D_DIM + ch * 32 + c4 * 4);
    }
    #pragma unroll
    for (int t = 0; t < 4; t++) {
        int i = tid + t * 256, row = i >> 3, c4 = i & 7;
        cpa16(sbase + (GB_OFF + buf * GS_A + row * 36 + c4 * 4) * 4,
              Bg + (size_t)row * D_DIM + ch * 32 + c4 * 4);
    }
    cpa_commit();
}

__device__ __forceinline__ void gemm128_core(
    const float* __restrict__ Ag, const float* __restrict__ Bg,
    float C[2][8][4], float* sm)
{
    const uint32_t sbase = smem_u32(sm);
    const int tid = threadIdx.x, wid = tid >> 5, lane = tid & 31;
    const int gq = lane >> 2, qi = lane & 3;
    const int wm = (wid >> 1) * 32, wn = (wid & 1) * 64;

    #pragma unroll
    for (int mi = 0; mi < 2; mi++)
        #pragma unroll
        for (int nt = 0; nt < 8; nt++)
            #pragma unroll
            for (int r = 0; r < 4; r++) C[mi][nt][r] = 0.f;

    gemm_stage(sbase, 0, Ag, Bg, 0);
    gemm_stage(sbase, 1, Ag, Bg, 1);

    int buf = 0, nbuf = 2;
    #pragma unroll 1
    for (int ch = 0; ch < 32; ch++) {
        if (ch == 31) cpa_wait<0>(); else cpa_wait<1>();
        __syncthreads();
        if (ch + 2 < 32) gemm_stage(sbase, nbuf, Ag, Bg, ch + 2);

        const float* as = sm + buf * GS_A;
        const float* bs = sm + GB_OFF + buf * GS_A;
        #pragma unroll
        for (int ks = 0; ks < 4; ks++) {
            uint32_t a[2][4];
            #pragma unroll
            for (int mi = 0; mi < 2; mi++) {
                const float* p = as + (wm + 16 * mi + gq) * 36 + 8 * ks + 2 * qi;
                float2 v0 = *(const float2*)p;            // (k, k+4) pair
                float2 v1 = *(const float2*)(p + 8 * 36); // row+8
                a[mi][0] = fbits(v0.x); a[mi][1] = fbits(v1.x);
                a[mi][2] = fbits(v0.y); a[mi][3] = fbits(v1.y);
            }
            #pragma unroll
            for (int nt = 0; nt < 8; nt++) {
                float2 vb = *(const float2*)(bs + (wn + 8 * nt + gq) * 36 + 8 * ks + 2 * qi);
                uint32_t b[2] = { fbits(vb.x), fbits(vb.y) };
                mma_tf32(C[0][nt], a[0], b);
                mma_tf32(C[1][nt], a[1], b);
            }
        }
        buf = (buf == 2) ? 0 : buf + 1;
        nbuf = (nbuf == 2) ? 0 : nbuf + 1;
    }
}

// ---------------------------------------------------------------------------
// Kernel 1: fused QKV projection. grid=(8, 32, 3)
// Q/K written hd-interleaved; V natural.
// ---------------------------------------------------------------------------
__global__ __launch_bounds__(256, 2) void qkv_kernel()
{
    extern __shared__ float sm[];
    const int z = blockIdx.z;
    const float* w = (z == 0) ? g_wqc : ((z == 1) ? g_wkc : g_wvc);
    const int m0 = blockIdx.y * 128, n0 = blockIdx.x * 128;

    float C[2][8][4];
    gemm128_core(g_xc + (size_t)m0 * D_DIM, w + (size_t)n0 * D_DIM, C, sm);

    float* dst = (z == 0) ? g_q : ((z == 1) ? g_k : g_v);
    const float scale = (z == 0) ? 0.125f : 1.0f;

    const int tid = threadIdx.x, wid = tid >> 5, lane = tid & 31;
    const int gq = lane >> 2, qi = lane & 3;
    const int wm = (wid >> 1) * 32, wn = (wid & 1) * 64;

    #pragma unroll
    for (int mi = 0; mi < 2; mi++)
        #pragma unroll
        for (int nt = 0; nt < 8; nt++) {
            int m = m0 + wm + 16 * mi + gq;
            int n = n0 + wn + 8 * nt + 2 * qi;
            int h = n >> 6, hd = n & 63, bb = m >> 11, s = m & (S_LEN - 1);
            float* p0 = dst + (((size_t)bb * NH + h) * S_LEN + s) * HDIM;
            float* p1 = dst + (((size_t)bb * NH + h) * S_LEN + s + 8) * HDIM;
            if (z < 2) {   // interleaved hd positions (scalar stores)
                int c0 = ilv8(hd), c1 = ilv8(hd + 1);
                p0[c0] = u2f(f2tf(C[mi][nt][0] * scale));
                p0[c1] = u2f(f2tf(C[mi][nt][1] * scale));
                p1[c0] = u2f(f2tf(C[mi][nt][2] * scale));
                p1[c1] = u2f(f2tf(C[mi][nt][3] * scale));
            } else {       // V natural
                *(float2*)(p0 + hd) = make_float2(u2f(f2tf(C[mi][nt][0])),
                                                  u2f(f2tf(C[mi][nt][1])));
                *(float2*)(p1 + hd) = make_float2(u2f(f2tf(C[mi][nt][2])),
                                                  u2f(f2tf(C[mi][nt][3])));
            }
        }
}

// ---------------------------------------------------------------------------
// Kernel 3: output projection + bias. grid=(8, 32)
// ---------------------------------------------------------------------------
__global__ __launch_bounds__(256, 2) void oproj_kernel(
    const float* __restrict__ bo, float* __restrict__ out)
{
    extern __shared__ float sm[];
    const int m0 = blockIdx.y * 128, n0 = blockIdx.x * 128;

    float C[2][8][4];
    gemm128_core(g_ctx + (size_t)m0 * D_DIM, g_woc + (size_t)n0 * D_DIM, C, sm);

    const int tid = threadIdx.x, wid = tid >> 5, lane = tid & 31;
    const int gq = lane >> 2, qi = lane & 3;
    const int wm = (wid >> 1) * 32, wn = (wid & 1) * 64;

    #pragma unroll
    for (int mi = 0; mi < 2; mi++)
        #pragma unroll
        for (int nt = 0; nt < 8; nt++) {
            int m = m0 + wm + 16 * mi + gq;
            int n = n0 + wn + 8 * nt + 2 * qi;
            float b0 = __ldg(bo + n), b1 = __ldg(bo + n + 1);
            *(float2*)(out + (size_t)m * D_DIM + n) =
                make_float2(C[mi][nt][0] + b0, C[mi][nt][1] + b1);
            *(float2*)(out + (size_t)(m + 8) * D_DIM + n) =
                make_float2(C[mi][nt][2] + b0, C[mi][nt][3] + b1);
        }
}

// ---------------------------------------------------------------------------
// Kernel 2: flash attention, 512 thr, 16 warps = 8(m of 16) x 2(kv half).
// Q/K interleaved (LDS.64 fragments); P in registers; K/V double-buffered.
// ---------------------------------------------------------------------------
#define AQ_OFF 0
#define AK_OFF 8704
#define AV_OFF (AK_OFF + 2 * 8704)
#define AR_OFF (AV_OFF + 2 * 9216)
#define ATTN_SMEM ((AR_OFF + 512) * 4)   // 180224 B

__device__ __forceinline__ void attn_prefetch(
    uint32_t sbase, const float* __restrict__ kp, const float* __restrict__ vp, int kt)
{
    const int tid = threadIdx.x;
    const int st = kt & 1;
    #pragma unroll
    for (int t = 0; t < 4; t++) {
        int i = tid + t * 512, row = i >> 4, c4 = i & 15;
        cpa16(sbase + (AK_OFF + st * 8704 + row * 68 + c4 * 4) * 4,
              kp + (size_t)(kt * 128 + row) * HDIM + c4 * 4);
    }
    #pragma unroll
    for (int t = 0; t < 4; t++) {
        int i = tid + t * 512, row = i >> 4, c4 = i & 15;
        cpa16(sbase + (AV_OFF + st * 9216 + row * 72 + c4 * 4) * 4,
              vp + (size_t)(kt * 128 + row) * HDIM + c4 * 4);
    }
    cpa_commit();
}

// C-fragment (exp'd scores) -> A-fragment for the PV mma, tf32-rounded.
__device__ __forceinline__ void p_to_afrag(const float c[4], uint32_t a[4], int lane) {
    const int qi = lane & 3;
    const int s0 = (lane & ~3) | (qi >> 1);
    const int s1 = s0 + 2;
    float t0 = __shfl_sync(0xffffffffu, c[0], s0);
    float t1 = __shfl_sync(0xffffffffu, c[1], s0);
    float t2 = __shfl_sync(0xffffffffu, c[2], s0);
    float t3 = __shfl_sync(0xffffffffu, c[3], s0);
    float u0 = __shfl_sync(0xffffffffu, c[0], s1);
    float u1 = __shfl_sync(0xffffffffu, c[1], s1);
    float u2 = __shfl_sync(0xffffffffu, c[2], s1);
    float u3 = __shfl_sync(0xffffffffu, c[3], s1);
    const bool odd = qi & 1;
    a[0] = f2tf(odd ? t1 : t0);
    a[1] = f2tf(odd ? t3 : t2);
    a[2] = f2tf(odd ? u1 : u0);
    a[3] = f2tf(odd ? u3 : u2);
}

__global__ __launch_bounds__(512, 1) void attn_kernel()
{
    extern __shared__ float sm[];
    float* Qs   = sm + AQ_OFF;           // [128][68]
    float* redm = sm + AR_OFF;           // [2][128]
    float* reds = redm + 256;            // [2][128]
    const uint32_t sbase = smem_u32(sm);

    const int bh = blockIdx.y, qt = blockIdx.x;
    const int tid = threadIdx.x, wid = tid >> 5, lane = tid & 31;
    const int gq = lane >> 2, qi = lane & 3;
    const int wm  = (wid >> 1) * 16;
    const int kvh = wid & 1;
    const int wn  = kvh * 64;

    const float* qp = g_q + ((size_t)bh * S_LEN + qt * 128) * HDIM;
    const float* kp = g_k + (size_t)bh * S_LEN * HDIM;
    const float* vp = g_v + (size_t)bh * S_LEN * HDIM;

    attn_prefetch(sbase, kp, vp, 0);
    #pragma unroll
    for (int t = 0; t < 4; t++) {
        int i = tid + t * 512, row = i >> 4, c4 = i & 15;
        *(float4*)(Qs + row * 68 + c4 * 4) =
            *(const float4*)(qp + (size_t)row * HDIM + c4 * 4);
    }

    float O[8][4];
    float m_i[2] = { -1e30f, -1e30f }, l_i[2] = { 0.f, 0.f };
    #pragma unroll
    for (int nt = 0; nt < 8; nt++)
        #pragma unroll
        for (int r = 0; r < 4; r++) O[nt][r] = 0.f;

    #pragma unroll 1
    for (int kt = 0; kt < S_LEN / 128; kt++) {
        cpa_wait<0>();
        __syncthreads();
        if (kt + 1 < S_LEN / 128) attn_prefetch(sbase, kp, vp, kt + 1);

        const float* ks = sm + AK_OFF + (kt & 1) * 8704;
        const float* vs = sm + AV_OFF + (kt & 1) * 9216;

        float Cs[8][4];
        #pragma unroll
        for (int nt = 0; nt < 8; nt++)
            #pragma unroll
            for (int r = 0; r < 4; r++) Cs[nt][r] = 0.f;

        #pragma unroll
        for (int ks_ = 0; ks_ < 8; ks_++) {
            uint32_t a[4];
            const float* p = Qs + (wm + gq) * 68 + 8 * ks_ + 2 * qi;
            float2 v0 = *(const float2*)p;
            float2 v1 = *(const float2*)(p + 8 * 68);
            a[0] = fbits(v0.x); a[1] = fbits(v1.x);
            a[2] = fbits(v0.y); a[3] = fbits(v1.y);
            #pragma unroll
            for (int nt = 0; nt < 8; nt++) {
                float2 vb = *(const float2*)(ks + (wn + 8 * nt + gq) * 68 + 8 * ks_ + 2 * qi);
                uint32_t b[2] = { fbits(vb.x), fbits(vb.y) };
                mma_tf32(Cs[nt], a, b);
            }
        }

        float rm0 = Cs[0][0], rm1 = Cs[0][2];
        #pragma unroll
        for (int nt = 0; nt < 8; nt++) {
            rm0 = fmaxf(rm0, fmaxf(Cs[nt][0], Cs[nt][1]));
            rm1 = fmaxf(rm1, fmaxf(Cs[nt][2], Cs[nt][3]));
        }
        rm0 = fmaxf(rm0, __shfl_xor_sync(0xffffffffu, rm0, 1));
        rm0 = fmaxf(rm0, __shfl_xor_sync(0xffffffffu, rm0, 2));
        rm1 = fmaxf(rm1, __shfl_xor_sync(0xffffffffu, rm1, 1));
        rm1 = fmaxf(rm1, __shfl_xor_sync(0xffffffffu, rm1, 2));
        if (qi == 0) {
            redm[kvh * 128 + wm + gq]     = rm0;
            redm[kvh * 128 + wm + gq + 8] = rm1;
        }
        __syncthreads();

        float mn0 = fmaxf(m_i[0], fmaxf(redm[wm + gq],     redm[128 + wm + gq]));
        float mn1 = fmaxf(m_i[1], fmaxf(redm[wm + gq + 8], redm[128 + wm + gq + 8]));
        float corr0 = __expf(m_i[0] - mn0), corr1 = __expf(m_i[1] - mn1);
        m_i[0] = mn0; m_i[1] = mn1;

        float ps0 = 0.f, ps1 = 0.f;
        #pragma unroll
        for (int nt = 0; nt < 8; nt++) {
            float e0 = __expf(Cs[nt][0] - mn0), e1 = __expf(Cs[nt][1] - mn0);
            float e2 = __expf(Cs[nt][2] - mn1), e3 = __expf(Cs[nt][3] - mn1);
            Cs[nt][0] = e0; Cs[nt][1] = e1; Cs[nt][2] = e2; Cs[nt][3] = e3;
            ps0 += e0 + e1; ps1 += e2 + e3;
        }
        ps0 += __shfl_xor_sync(0xffffffffu, ps0, 1);
        ps0 += __shfl_xor_sync(0xffffffffu, ps0, 2);
        ps1 += __shfl_xor_sync(0xffffffffu, ps1, 1);
        ps1 += __shfl_xor_sync(0xffffffffu, ps1, 2);
        if (qi == 0) {
            reds[kvh * 128 + wm + gq]     = ps0;
            reds[kvh * 128 + wm + gq + 8] = ps1;
        }

        #pragma unroll
        for (int nt = 0; nt < 8; nt++) {
            O[nt][0] *= corr0; O[nt][1] *= corr0;
            O[nt][2] *= corr1; O[nt][3] *= corr1;
        }
        __syncthreads();

        l_i[0] = l_i[0] * corr0 + reds[wm + gq]     + reds[128 + wm + gq];
        l_i[1] = l_i[1] * corr1 + reds[wm + gq + 8] + reds[128 + wm + gq + 8];

        #pragma unroll
        for (int kc = 0; kc < 8; kc++) {
            uint32_t a[4];
            p_to_afrag(Cs[kc], a, lane);
            const float* pv = vs + (size_t)(wn + 8 * kc + qi) * 72 + gq;
            #pragma unroll
            for (int nt = 0; nt < 8; nt++) {
                uint32_t b[2] = { fbits(pv[8 * nt]), fbits(pv[4 * 72 + 8 * nt]) };
                mma_tf32(O[nt], a, b);
            }
        }
    }

    // Combine kv-halves, normalize, write ctx [b,s,h,hd~] (interleaved for oproj)
    __syncthreads();
    float* Os = Qs;
    if (kvh == 1) {
        #pragma unroll
        for (int nt = 0; nt < 8; nt++) {
            int cc = 8 * nt + 2 * qi;
            *(float2*)(Os + (wm + gq) * 68 + cc)     = make_float2(O[nt][0], O[nt][1]);
            *(float2*)(Os + (wm + gq + 8) * 68 + cc) = make_float2(O[nt][2], O[nt][3]);
        }
    }
    __syncthreads();
    if (kvh == 0) {
        const int b_ = bh >> 4, h = bh & 15;
        const float inv0 = 1.f / l_i[0], inv1 = 1.f / l_i[1];
        const int s = qt * 128 + wm + gq;
        #pragma unroll
        for (int nt = 0; nt < 8; nt++) {
            int cc = 8 * nt + 2 * qi;
            int c0 = ilv8(cc), c1 = ilv8(cc + 1);
            float2 q0 = *(float2*)(Os + (wm + gq) * 68 + cc);
            float2 q1 = *(float2*)(Os + (wm + gq + 8) * 68 + cc);
            float* p0 = g_ctx + (((size_t)b_ * S_LEN + s) * NH + h) * HDIM;
            float* p1 = g_ctx + (((size_t)b_ * S_LEN + s + 8) * NH + h) * HDIM;
            p0[c0] = u2f(f2tf((O[nt][0] + q0.x) * inv0));
            p0[c1] = u2f(f2tf((O[nt][1] + q0.y) * inv0));
            p1[c0] = u2f(f2tf((O[nt][2] + q1.x) * inv1));
            p1[c1] = u2f(f2tf((O[nt][3] + q1.y) * inv1));
        }
    }
}

// ---------------------------------------------------------------------------
extern "C" void kernel_launch(void* const* d_in, const int* in_sizes, int n_in,
                              void* d_out, int out_size)
{
    const float* x  = (const float*)d_in[0];
    const float* wq = (const float*)d_in[1];
    const float* wk = (const float*)d_in[2];
    const float* wv = (const float*)d_in[3];
    const float* wo = (const float*)d_in[4];
    const float* bo = (const float*)d_in[5];
    float* out = (float*)d_out;

    cudaFuncSetAttribute(qkv_kernel,   cudaFuncAttributeMaxDynamicSharedMemorySize, GEMM_SMEM);
    cudaFuncSetAttribute(oproj_kernel, cudaFuncAttributeMaxDynamicSharedMemorySize, GEMM_SMEM);
    cudaFuncSetAttribute(attn_kernel,  cudaFuncAttributeMaxDynamicSharedMemorySize, ATTN_SMEM);

    prep_kernel<<<dim3(256, 5), 256>>>(x, wq, wk, wv, wo);
    qkv_kernel<<<dim3(D_DIM / 128, M_TOT / 128, 3), 256, GEMM_SMEM>>>();
    attn_kernel<<<dim3(S_LEN / 128, NB * NH), 512, ATTN_SMEM>>>();
    oproj_kernel<<<dim3(D_DIM / 128, M_TOT / 128), 256, GEMM_SMEM>>>(bo, out);
}

// round 7
// speedup vs baseline: 1.2857x; 1.2857x over previous
#include <cuda_runtime.h>
#include <cstdint>

#define S_LEN 2048
#define D_DIM 1024
#define NH    16
#define HDIM  64
#define NB    2
#define M_TOT 4096

// Scratch (all tf32-rounded where consumed by mma)
__device__ float g_q[NB * NH * S_LEN * HDIM];   // [b,h,s,hd], 0.125-scaled
__device__ float g_k[NB * NH * S_LEN * HDIM];
__device__ float g_v[NB * NH * S_LEN * HDIM];
__device__ float g_ctx[NB * S_LEN * D_DIM];     // [b,s,d]
__device__ float g_xc[M_TOT * D_DIM];
__device__ float g_wqc[D_DIM * D_DIM];
__device__ float g_wkc[D_DIM * D_DIM];
__device__ float g_wvc[D_DIM * D_DIM];
__device__ float g_woc[D_DIM * D_DIM];

// ---------------------------------------------------------------------------
__device__ __forceinline__ uint32_t f2tf(float f) {
    uint32_t u;
    asm("cvt.rna.tf32.f32 %0, %1;" : "=r"(u) : "f"(f));
    return u;
}
__device__ __forceinline__ float u2f(uint32_t u) { return __uint_as_float(u); }
__device__ __forceinline__ uint32_t fbits(float f) { return __float_as_uint(f); }

__device__ __forceinline__ uint32_t smem_u32(const void* p) {
    uint32_t a;
    asm("{ .reg .u64 t; cvta.to.shared.u64 t, %1; cvt.u32.u64 %0, t; }" : "=r"(a) : "l"(p));
    return a;
}
__device__ __forceinline__ void mma_tf32(float d[4], const uint32_t a[4], const uint32_t b[2]) {
    asm("mma.sync.aligned.m16n8k8.row.col.f32.tf32.tf32.f32 "
        "{%0,%1,%2,%3}, {%4,%5,%6,%7}, {%8,%9}, {%0,%1,%2,%3};"
        : "+f"(d[0]), "+f"(d[1]), "+f"(d[2]), "+f"(d[3])
        : "r"(a[0]), "r"(a[1]), "r"(a[2]), "r"(a[3]), "r"(b[0]), "r"(b[1]));
}
__device__ __forceinline__ void cpa16(uint32_t dst, const void* src) {
    asm volatile("cp.async.ca.shared.global [%0], [%1], 16;" :: "r"(dst), "l"(src) : "memory");
}
__device__ __forceinline__ void cpa_commit() {
    asm volatile("cp.async.commit_group;" ::: "memory");
}
template <int N>
__device__ __forceinline__ void cpa_wait() {
    asm volatile("cp.async.wait_group %0;" :: "n"(N) : "memory");
}

// ---------------------------------------------------------------------------
// Prep: tf32-round x and all weights once.
// ---------------------------------------------------------------------------
__global__ __launch_bounds__(256) void prep_kernel(
    const float* __restrict__ x,  const float* __restrict__ wq,
    const float* __restrict__ wk, const float* __restrict__ wv,
    const float* __restrict__ wo)
{
    const float* src; float* dst; int n4;
    switch (blockIdx.y) {
        case 0: src = x;  dst = g_xc;  n4 = M_TOT * D_DIM / 4; break;
        case 1: src = wq; dst = g_wqc; n4 = D_DIM * D_DIM / 4; break;
        case 2: src = wk; dst = g_wkc; n4 = D_DIM * D_DIM / 4; break;
        case 3: src = wv; dst = g_wvc; n4 = D_DIM * D_DIM / 4; break;
        default: src = wo; dst = g_woc; n4 = D_DIM * D_DIM / 4; break;
    }
    const int stride = gridDim.x * blockDim.x;
    for (int i = blockIdx.x * blockDim.x + threadIdx.x; i < n4; i += stride) {
        float4 v = __ldg((const float4*)src + i);
        ((float4*)dst)[i] = make_float4(u2f(f2tf(v.x)), u2f(f2tf(v.y)),
                                        u2f(f2tf(v.z)), u2f(f2tf(v.w)));
    }
}

// ---------------------------------------------------------------------------
// GEMM core v2: D[128,256] = A[128,1024] @ B[256,1024]^T, tf32 pre-rounded.
// 256 thr, 8 warps = 2(m) x 4(n); warp tile 64x64; 3-stage cp.async.
// Per ks-step: 32 LDS.32 -> 32 mmas (1.0 LDS/mma).
// ---------------------------------------------------------------------------
#define GSA 4608                        // A stage floats (128*36)
#define GSB 9216                        // B stage floats (256*36)
#define GB_OFF (3 * GSA)
#define GEMM_SMEM ((3 * GSA + 3 * GSB) * 4)   // 165888 B

__device__ __forceinline__ void gemm_stage(
    uint32_t sbase, int buf, const float* __restrict__ Ag,
    const float* __restrict__ Bg, int ch)
{
    const int tid = threadIdx.x;
    #pragma unroll
    for (int t = 0; t < 4; t++) {       // A: 128 rows x 32 k
        int i = tid + t * 256, row = i >> 3, c4 = i & 7;
        cpa16(sbase + (buf * GSA + row * 36 + c4 * 4) * 4,
              Ag + (size_t)row * D_DIM + ch * 32 + c4 * 4);
    }
    #pragma unroll
    for (int t = 0; t < 8; t++) {       // B: 256 rows x 32 k
        int i = tid + t * 256, row = i >> 3, c4 = i & 7;
        cpa16(sbase + (GB_OFF + buf * GSB + row * 36 + c4 * 4) * 4,
              Bg + (size_t)row * D_DIM + ch * 32 + c4 * 4);
    }
    cpa_commit();
}

__device__ __forceinline__ void gemm128_core(
    const float* __restrict__ Ag, const float* __restrict__ Bg,
    float C[4][8][4], float* sm)
{
    const uint32_t sbase = smem_u32(sm);
    const int tid = threadIdx.x, wid = tid >> 5, lane = tid & 31;
    const int gq = lane >> 2, qi = lane & 3;
    const int wm = (wid >> 2) * 64, wn = (wid & 3) * 64;

    #pragma unroll
    for (int mi = 0; mi < 4; mi++)
        #pragma unroll
        for (int nt = 0; nt < 8; nt++)
            #pragma unroll
            for (int r = 0; r < 4; r++) C[mi][nt][r] = 0.f;

    gemm_stage(sbase, 0, Ag, Bg, 0);
    gemm_stage(sbase, 1, Ag, Bg, 1);

    int buf = 0, nbuf = 2;
    #pragma unroll 1
    for (int ch = 0; ch < 32; ch++) {
        if (ch == 31) cpa_wait<0>(); else cpa_wait<1>();
        __syncthreads();
        if (ch + 2 < 32) gemm_stage(sbase, nbuf, Ag, Bg, ch + 2);

        const float* as = sm + buf * GSA;
        const float* bs = sm + GB_OFF + buf * GSB;
        #pragma unroll
        for (int ks = 0; ks < 4; ks++) {
            uint32_t a[4][4];
            #pragma unroll
            for (int mi = 0; mi < 4; mi++) {
                const float* p = as + (wm + 16 * mi + gq) * 36 + 8 * ks + qi;
                a[mi][0] = fbits(p[0]);
                a[mi][1] = fbits(p[8 * 36]);
                a[mi][2] = fbits(p[4]);
                a[mi][3] = fbits(p[8 * 36 + 4]);
            }
            #pragma unroll
            for (int nt = 0; nt < 8; nt++) {
                const float* p = bs + (wn + 8 * nt + gq) * 36 + 8 * ks + qi;
                uint32_t b[2] = { fbits(p[0]), fbits(p[4]) };
                #pragma unroll
                for (int mi = 0; mi < 4; mi++)
                    mma_tf32(C[mi][nt], a[mi], b);
            }
        }
        buf = (buf == 2) ? 0 : buf + 1;
        nbuf = (nbuf == 2) ? 0 : nbuf + 1;
    }
}

// ---------------------------------------------------------------------------
// Kernel 1: fused QKV projection. grid=(4, 32, 3), CTA tile 128x256.
// ---------------------------------------------------------------------------
__global__ __launch_bounds__(256, 1) void qkv_kernel()
{
    extern __shared__ float sm[];
    const int z = blockIdx.z;
    const float* w = (z == 0) ? g_wqc : ((z == 1) ? g_wkc : g_wvc);
    const int m0 = blockIdx.y * 128, n0 = blockIdx.x * 256;

    float C[4][8][4];
    gemm128_core(g_xc + (size_t)m0 * D_DIM, w + (size_t)n0 * D_DIM, C, sm);

    float* dst = (z == 0) ? g_q : ((z == 1) ? g_k : g_v);
    const float scale = (z == 0) ? 0.125f : 1.0f;

    const int tid = threadIdx.x, wid = tid >> 5, lane = tid & 31;
    const int gq = lane >> 2, qi = lane & 3;
    const int wm = (wid >> 2) * 64, wn = (wid & 3) * 64;

    #pragma unroll
    for (int mi = 0; mi < 4; mi++)
        #pragma unroll
        for (int nt = 0; nt < 8; nt++) {
            int m = m0 + wm + 16 * mi + gq;
            int n = n0 + wn + 8 * nt + 2 * qi;
            int h = n >> 6, hd = n & 63, bb = m >> 11, s = m & (S_LEN - 1);
            float* p0 = dst + (((size_t)bb * NH + h) * S_LEN + s) * HDIM + hd;
            float* p1 = dst + (((size_t)bb * NH + h) * S_LEN + s + 8) * HDIM + hd;
            *(float2*)p0 = make_float2(u2f(f2tf(C[mi][nt][0] * scale)),
                                       u2f(f2tf(C[mi][nt][1] * scale)));
            *(float2*)p1 = make_float2(u2f(f2tf(C[mi][nt][2] * scale)),
                                       u2f(f2tf(C[mi][nt][3] * scale)));
        }
}

// ---------------------------------------------------------------------------
// Kernel 3: output projection + bias. grid=(4, 32)
// ---------------------------------------------------------------------------
__global__ __launch_bounds__(256, 1) void oproj_kernel(
    const float* __restrict__ bo, float* __restrict__ out)
{
    extern __shared__ float sm[];
    const int m0 = blockIdx.y * 128, n0 = blockIdx.x * 256;

    float C[4][8][4];
    gemm128_core(g_ctx + (size_t)m0 * D_DIM, g_woc + (size_t)n0 * D_DIM, C, sm);

    const int tid = threadIdx.x, wid = tid >> 5, lane = tid & 31;
    const int gq = lane >> 2, qi = lane & 3;
    const int wm = (wid >> 2) * 64, wn = (wid & 3) * 64;

    #pragma unroll
    for (int mi = 0; mi < 4; mi++)
        #pragma unroll
        for (int nt = 0; nt < 8; nt++) {
            int m = m0 + wm + 16 * mi + gq;
            int n = n0 + wn + 8 * nt + 2 * qi;
            float b0 = __ldg(bo + n), b1 = __ldg(bo + n + 1);
            *(float2*)(out + (size_t)m * D_DIM + n) =
                make_float2(C[mi][nt][0] + b0, C[mi][nt][1] + b1);
            *(float2*)(out + (size_t)(m + 8) * D_DIM + n) =
                make_float2(C[mi][nt][2] + b0, C[mi][nt][3] + b1);
        }
}

// ---------------------------------------------------------------------------
// Kernel 2: flash attention — identical to round-5 version (586us baseline).
// 512 thr, 16 warps = 8(m of 16 rows) x 2(kv half); P in registers;
// K/V cp.async double-buffered; O combined across kv-halves via SMEM.
// ---------------------------------------------------------------------------
#define AQ_OFF 0
#define AK_OFF 8704
#define AV_OFF (AK_OFF + 2 * 8704)
#define AR_OFF (AV_OFF + 2 * 9216)
#define ATTN_SMEM ((AR_OFF + 512) * 4)   // 180224 B

__device__ __forceinline__ void attn_prefetch(
    uint32_t sbase, const float* __restrict__ kp, const float* __restrict__ vp, int kt)
{
    const int tid = threadIdx.x;
    const int st = kt & 1;
    #pragma unroll
    for (int t = 0; t < 4; t++) {
        int i = tid + t * 512, row = i >> 4, c4 = i & 15;
        cpa16(sbase + (AK_OFF + st * 8704 + row * 68 + c4 * 4) * 4,
              kp + (size_t)(kt * 128 + row) * HDIM + c4 * 4);
    }
    #pragma unroll
    for (int t = 0; t < 4; t++) {
        int i = tid + t * 512, row = i >> 4, c4 = i & 15;
        cpa16(sbase + (AV_OFF + st * 9216 + row * 72 + c4 * 4) * 4,
              vp + (size_t)(kt * 128 + row) * HDIM + c4 * 4);
    }
    cpa_commit();
}

__device__ __forceinline__ void p_to_afrag(const float c[4], uint32_t a[4], int lane) {
    const int qi = lane & 3;
    const int s0 = (lane & ~3) | (qi >> 1);
    const int s1 = s0 + 2;
    float t0 = __shfl_sync(0xffffffffu, c[0], s0);
    float t1 = __shfl_sync(0xffffffffu, c[1], s0);
    float t2 = __shfl_sync(0xffffffffu, c[2], s0);
    float t3 = __shfl_sync(0xffffffffu, c[3], s0);
    float u0 = __shfl_sync(0xffffffffu, c[0], s1);
    float u1 = __shfl_sync(0xffffffffu, c[1], s1);
    float u2 = __shfl_sync(0xffffffffu, c[2], s1);
    float u3 = __shfl_sync(0xffffffffu, c[3], s1);
    const bool odd = qi & 1;
    a[0] = f2tf(odd ? t1 : t0);
    a[1] = f2tf(odd ? t3 : t2);
    a[2] = f2tf(odd ? u1 : u0);
    a[3] = f2tf(odd ? u3 : u2);
}

__global__ __launch_bounds__(512, 1) void attn_kernel()
{
    extern __shared__ float sm[];
    float* Qs   = sm + AQ_OFF;
    float* redm = sm + AR_OFF;
    float* reds = redm + 256;
    const uint32_t sbase = smem_u32(sm);

    const int bh = blockIdx.y, qt = blockIdx.x;
    const int tid = threadIdx.x, wid = tid >> 5, lane = tid & 31;
    const int gq = lane >> 2, qi = lane & 3;
    const int wm  = (wid >> 1) * 16;
    const int kvh = wid & 1;
    const int wn  = kvh * 64;

    const float* qp = g_q + ((size_t)bh * S_LEN + qt * 128) * HDIM;
    const float* kp = g_k + (size_t)bh * S_LEN * HDIM;
    const float* vp = g_v + (size_t)bh * S_LEN * HDIM;

    attn_prefetch(sbase, kp, vp, 0);
    #pragma unroll
    for (int t = 0; t < 4; t++) {
        int i = tid + t * 512, row = i >> 4, c4 = i & 15;
        *(float4*)(Qs + row * 68 + c4 * 4) =
            *(const float4*)(qp + (size_t)row * HDIM + c4 * 4);
    }

    float O[8][4];
    float m_i[2] = { -1e30f, -1e30f }, l_i[2] = { 0.f, 0.f };
    #pragma unroll
    for (int nt = 0; nt < 8; nt++)
        #pragma unroll
        for (int r = 0; r < 4; r++) O[nt][r] = 0.f;

    #pragma unroll 1
    for (int kt = 0; kt < S_LEN / 128; kt++) {
        cpa_wait<0>();
        __syncthreads();
        if (kt + 1 < S_LEN / 128) attn_prefetch(sbase, kp, vp, kt + 1);

        const float* ks = sm + AK_OFF + (kt & 1) * 8704;
        const float* vs = sm + AV_OFF + (kt & 1) * 9216;

        float Cs[8][4];
        #pragma unroll
        for (int nt = 0; nt < 8; nt++)
            #pragma unroll
            for (int r = 0; r < 4; r++) Cs[nt][r] = 0.f;

        #pragma unroll
        for (int ks_ = 0; ks_ < 8; ks_++) {
            uint32_t a[4];
            const float* p = Qs + (wm + gq) * 68 + 8 * ks_ + qi;
            a[0] = fbits(p[0]);
            a[1] = fbits(p[8 * 68]);
            a[2] = fbits(p[4]);
            a[3] = fbits(p[8 * 68 + 4]);
            #pragma unroll
            for (int nt = 0; nt < 8; nt++) {
                const float* pb = ks + (wn + 8 * nt + gq) * 68 + 8 * ks_ + qi;
                uint32_t b[2] = { fbits(pb[0]), fbits(pb[4]) };
                mma_tf32(Cs[nt], a, b);
            }
        }

        float rm0 = Cs[0][0], rm1 = Cs[0][2];
        #pragma unroll
        for (int nt = 0; nt < 8; nt++) {
            rm0 = fmaxf(rm0, fmaxf(Cs[nt][0], Cs[nt][1]));
            rm1 = fmaxf(rm1, fmaxf(Cs[nt][2], Cs[nt][3]));
        }
        rm0 = fmaxf(rm0, __shfl_xor_sync(0xffffffffu, rm0, 1));
        rm0 = fmaxf(rm0, __shfl_xor_sync(0xffffffffu, rm0, 2));
        rm1 = fmaxf(rm1, __shfl_xor_sync(0xffffffffu, rm1, 1));
        rm1 = fmaxf(rm1, __shfl_xor_sync(0xffffffffu, rm1, 2));
        if (qi == 0) {
            redm[kvh * 128 + wm + gq]     = rm0;
            redm[kvh * 128 + wm + gq + 8] = rm1;
        }
        __syncthreads();

        float mn0 = fmaxf(m_i[0], fmaxf(redm[wm + gq],     redm[128 + wm + gq]));
        float mn1 = fmaxf(m_i[1], fmaxf(redm[wm + gq + 8], redm[128 + wm + gq + 8]));
        float corr0 = __expf(m_i[0] - mn0), corr1 = __expf(m_i[1] - mn1);
        m_i[0] = mn0; m_i[1] = mn1;

        float ps0 = 0.f, ps1 = 0.f;
        #pragma unroll
        for (int nt = 0; nt < 8; nt++) {
            float e0 = __expf(Cs[nt][0] - mn0), e1 = __expf(Cs[nt][1] - mn0);
            float e2 = __expf(Cs[nt][2] - mn1), e3 = __expf(Cs[nt][3] - mn1);
            Cs[nt][0] = e0; Cs[nt][1] = e1; Cs[nt][2] = e2; Cs[nt][3] = e3;
            ps0 += e0 + e1; ps1 += e2 + e3;
        }
        ps0 += __shfl_xor_sync(0xffffffffu, ps0, 1);
        ps0 += __shfl_xor_sync(0xffffffffu, ps0, 2);
        ps1 += __shfl_xor_sync(0xffffffffu, ps1, 1);
        ps1 += __shfl_xor_sync(0xffffffffu, ps1, 2);
        if (qi == 0) {
            reds[kvh * 128 + wm + gq]     = ps0;
            reds[kvh * 128 + wm + gq + 8] = ps1;
        }

        #pragma unroll
        for (int nt = 0; nt < 8; nt++) {
            O[nt][0] *= corr0; O[nt][1] *= corr0;
            O[nt][2] *= corr1; O[nt][3] *= corr1;
        }
        __syncthreads();

        l_i[0] = l_i[0] * corr0 + reds[wm + gq]     + reds[128 + wm + gq];
        l_i[1] = l_i[1] * corr1 + reds[wm + gq + 8] + reds[128 + wm + gq + 8];

        #pragma unroll
        for (int kc = 0; kc < 8; kc++) {
            uint32_t a[4];
            p_to_afrag(Cs[kc], a, lane);
            const float* pv = vs + (size_t)(wn + 8 * kc + qi) * 72 + gq;
            #pragma unroll
            for (int nt = 0; nt < 8; nt++) {
                uint32_t b[2] = { fbits(pv[8 * nt]), fbits(pv[4 * 72 + 8 * nt]) };
                mma_tf32(O[nt], a, b);
            }
        }
    }

    __syncthreads();
    float* Os = Qs;
    if (kvh == 1) {
        #pragma unroll
        for (int nt = 0; nt < 8; nt++) {
            int cc = 8 * nt + 2 * qi;
            *(float2*)(Os + (wm + gq) * 68 + cc)     = make_float2(O[nt][0], O[nt][1]);
            *(float2*)(Os + (wm + gq + 8) * 68 + cc) = make_float2(O[nt][2], O[nt][3]);
        }
    }
    __syncthreads();
    if (kvh == 0) {
        const int b_ = bh >> 4, h = bh & 15;
        const float inv0 = 1.f / l_i[0], inv1 = 1.f / l_i[1];
        const int s = qt * 128 + wm + gq;
        #pragma unroll
        for (int nt = 0; nt < 8; nt++) {
            int cc = 8 * nt + 2 * qi;
            float2 q0 = *(float2*)(Os + (wm + gq) * 68 + cc);
            float2 q1 = *(float2*)(Os + (wm + gq + 8) * 68 + cc);
            float* p0 = g_ctx + (((size_t)b_ * S_LEN + s) * NH + h) * HDIM + cc;
            float* p1 = g_ctx + (((size_t)b_ * S_LEN + s + 8) * NH + h) * HDIM + cc;
            *(float2*)p0 = make_float2(u2f(f2tf((O[nt][0] + q0.x) * inv0)),
                                       u2f(f2tf((O[nt][1] + q0.y) * inv0)));
            *(float2*)p1 = make_float2(u2f(f2tf((O[nt][2] + q1.x) * inv1)),
                                       u2f(f2tf((O[nt][3] + q1.y) * inv1)));
        }
    }
}

// ---------------------------------------------------------------------------
extern "C" void kernel_launch(void* const* d_in, const int* in_sizes, int n_in,
                              void* d_out, int out_size)
{
    const float* x  = (const float*)d_in[0];
    const float* wq = (const float*)d_in[1];
    const float* wk = (const float*)d_in[2];
    const float* wv = (const float*)d_in[3];
    const float* wo = (const float*)d_in[4];
    const float* bo = (const float*)d_in[5];
    float* out = (float*)d_out;

    cudaFuncSetAttribute(qkv_kernel,   cudaFuncAttributeMaxDynamicSharedMemorySize, GEMM_SMEM);
    cudaFuncSetAttribute(oproj_kernel, cudaFuncAttributeMaxDynamicSharedMemorySize, GEMM_SMEM);
    cudaFuncSetAttribute(attn_kernel,  cudaFuncAttributeMaxDynamicSharedMemorySize, ATTN_SMEM);

    prep_kernel<<<dim3(256, 5), 256>>>(x, wq, wk, wv, wo);
    qkv_kernel<<<dim3(D_DIM / 256, M_TOT / 128, 3), 256, GEMM_SMEM>>>();
    attn_kernel<<<dim3(S_LEN / 128, NB * NH), 512, ATTN_SMEM>>>();
    oproj_kernel<<<dim3(D_DIM / 256, M_TOT / 128), 256, GEMM_SMEM>>>(bo, out);
}

// round 8
// speedup vs baseline: 1.4308x; 1.1129x over previous
#include <cuda_runtime.h>
#include <cstdint>

#define S_LEN 2048
#define D_DIM 1024
#define NH    16
#define HDIM  64
#define NB    2
#define M_TOT 4096

// Scratch (all tf32-rounded where consumed by mma)
__device__ float g_q[NB * NH * S_LEN * HDIM];   // [b,h,s,hd], 0.125-scaled
__device__ float g_k[NB * NH * S_LEN * HDIM];
__device__ float g_v[NB * NH * S_LEN * HDIM];
__device__ float g_ctx[NB * S_LEN * D_DIM];     // [b,s,d]
__device__ float g_xc[M_TOT * D_DIM];
__device__ float g_wqc[D_DIM * D_DIM];
__device__ float g_wkc[D_DIM * D_DIM];
__device__ float g_wvc[D_DIM * D_DIM];
__device__ float g_woc[D_DIM * D_DIM];

// ---------------------------------------------------------------------------
__device__ __forceinline__ uint32_t f2tf(float f) {
    uint32_t u;
    asm("cvt.rna.tf32.f32 %0, %1;" : "=r"(u) : "f"(f));
    return u;
}
__device__ __forceinline__ float u2f(uint32_t u) { return __uint_as_float(u); }
__device__ __forceinline__ uint32_t fbits(float f) { return __float_as_uint(f); }

__device__ __forceinline__ uint32_t smem_u32(const void* p) {
    uint32_t a;
    asm("{ .reg .u64 t; cvta.to.shared.u64 t, %1; cvt.u32.u64 %0, t; }" : "=r"(a) : "l"(p));
    return a;
}
__device__ __forceinline__ void mma_tf32(float d[4], const uint32_t a[4], const uint32_t b[2]) {
    asm("mma.sync.aligned.m16n8k8.row.col.f32.tf32.tf32.f32 "
        "{%0,%1,%2,%3}, {%4,%5,%6,%7}, {%8,%9}, {%0,%1,%2,%3};"
        : "+f"(d[0]), "+f"(d[1]), "+f"(d[2]), "+f"(d[3])
        : "r"(a[0]), "r"(a[1]), "r"(a[2]), "r"(a[3]), "r"(b[0]), "r"(b[1]));
}
__device__ __forceinline__ void cpa16(uint32_t dst, const void* src) {
    asm volatile("cp.async.ca.shared.global [%0], [%1], 16;" :: "r"(dst), "l"(src) : "memory");
}
__device__ __forceinline__ void cpa_commit() {
    asm volatile("cp.async.commit_group;" ::: "memory");
}
template <int N>
__device__ __forceinline__ void cpa_wait() {
    asm volatile("cp.async.wait_group %0;" :: "n"(N) : "memory");
}

// ---------------------------------------------------------------------------
// Prep: tf32-round x and all weights once.
// ---------------------------------------------------------------------------
__global__ __launch_bounds__(256) void prep_kernel(
    const float* __restrict__ x,  const float* __restrict__ wq,
    const float* __restrict__ wk, const float* __restrict__ wv,
    const float* __restrict__ wo)
{
    const float* src; float* dst; int n4;
    switch (blockIdx.y) {
        case 0: src = x;  dst = g_xc;  n4 = M_TOT * D_DIM / 4; break;
        case 1: src = wq; dst = g_wqc; n4 = D_DIM * D_DIM / 4; break;
        case 2: src = wk; dst = g_wkc; n4 = D_DIM * D_DIM / 4; break;
        case 3: src = wv; dst = g_wvc; n4 = D_DIM * D_DIM / 4; break;
        default: src = wo; dst = g_woc; n4 = D_DIM * D_DIM / 4; break;
    }
    const int stride = gridDim.x * blockDim.x;
    for (int i = blockIdx.x * blockDim.x + threadIdx.x; i < n4; i += stride) {
        float4 v = __ldg((const float4*)src + i);
        ((float4*)dst)[i] = make_float4(u2f(f2tf(v.x)), u2f(f2tf(v.y)),
                                        u2f(f2tf(v.z)), u2f(f2tf(v.w)));
    }
}

// ---------------------------------------------------------------------------
// GEMM core (unchanged from R7): D[128,256] = A[128,1024] @ B[256,1024]^T.
// 256 thr, 8 warps = 2(m) x 4(n); warp tile 64x64; 3-stage cp.async.
// ---------------------------------------------------------------------------
#define GSA 4608
#define GSB 9216
#define GB_OFF (3 * GSA)
#define GEMM_SMEM ((3 * GSA + 3 * GSB) * 4)   // 165888 B

__device__ __forceinline__ void gemm_stage(
    uint32_t sbase, int buf, const float* __restrict__ Ag,
    const float* __restrict__ Bg, int ch)
{
    const int tid = threadIdx.x;
    #pragma unroll
    for (int t = 0; t < 4; t++) {
        int i = tid + t * 256, row = i >> 3, c4 = i & 7;
        cpa16(sbase + (buf * GSA + row * 36 + c4 * 4) * 4,
              Ag + (size_t)row * D_DIM + ch * 32 + c4 * 4);
    }
    #pragma unroll
    for (int t = 0; t < 8; t++) {
        int i = tid + t * 256, row = i >> 3, c4 = i & 7;
        cpa16(sbase + (GB_OFF + buf * GSB + row * 36 + c4 * 4) * 4,
              Bg + (size_t)row * D_DIM + ch * 32 + c4 * 4);
    }
    cpa_commit();
}

__device__ __forceinline__ void gemm128_core(
    const float* __restrict__ Ag, const float* __restrict__ Bg,
    float C[4][8][4], float* sm)
{
    const uint32_t sbase = smem_u32(sm);
    const int tid = threadIdx.x, wid = tid >> 5, lane = tid & 31;
    const int gq = lane >> 2, qi = lane & 3;
    const int wm = (wid >> 2) * 64, wn = (wid & 3) * 64;

    #pragma unroll
    for (int mi = 0; mi < 4; mi++)
        #pragma unroll
        for (int nt = 0; nt < 8; nt++)
            #pragma unroll
            for (int r = 0; r < 4; r++) C[mi][nt][r] = 0.f;

    gemm_stage(sbase, 0, Ag, Bg, 0);
    gemm_stage(sbase, 1, Ag, Bg, 1);

    int buf = 0, nbuf = 2;
    #pragma unroll 1
    for (int ch = 0; ch < 32; ch++) {
        if (ch == 31) cpa_wait<0>(); else cpa_wait<1>();
        __syncthreads();
        if (ch + 2 < 32) gemm_stage(sbase, nbuf, Ag, Bg, ch + 2);

        const float* as = sm + buf * GSA;
        const float* bs = sm + GB_OFF + buf * GSB;
        #pragma unroll
        for (int ks = 0; ks < 4; ks++) {
            uint32_t a[4][4];
            #pragma unroll
            for (int mi = 0; mi < 4; mi++) {
                const float* p = as + (wm + 16 * mi + gq) * 36 + 8 * ks + qi;
                a[mi][0] = fbits(p[0]);
                a[mi][1] = fbits(p[8 * 36]);
                a[mi][2] = fbits(p[4]);
                a[mi][3] = fbits(p[8 * 36 + 4]);
            }
            #pragma unroll
            for (int nt = 0; nt < 8; nt++) {
                const float* p = bs + (wn + 8 * nt + gq) * 36 + 8 * ks + qi;
                uint32_t b[2] = { fbits(p[0]), fbits(p[4]) };
                #pragma unroll
                for (int mi = 0; mi < 4; mi++)
                    mma_tf32(C[mi][nt], a[mi], b);
            }
        }
        buf = (buf == 2) ? 0 : buf + 1;
        nbuf = (nbuf == 2) ? 0 : nbuf + 1;
    }
}

// ---------------------------------------------------------------------------
// Kernel 1: fused QKV projection. grid=(4, 32, 3), CTA tile 128x256.
// ---------------------------------------------------------------------------
__global__ __launch_bounds__(256, 1) void qkv_kernel()
{
    extern __shared__ float sm[];
    const int z = blockIdx.z;
    const float* w = (z == 0) ? g_wqc : ((z == 1) ? g_wkc : g_wvc);
    const int m0 = blockIdx.y * 128, n0 = blockIdx.x * 256;

    float C[4][8][4];
    gemm128_core(g_xc + (size_t)m0 * D_DIM, w + (size_t)n0 * D_DIM, C, sm);

    float* dst = (z == 0) ? g_q : ((z == 1) ? g_k : g_v);
    const float scale = (z == 0) ? 0.125f : 1.0f;

    const int tid = threadIdx.x, wid = tid >> 5, lane = tid & 31;
    const int gq = lane >> 2, qi = lane & 3;
    const int wm = (wid >> 2) * 64, wn = (wid & 3) * 64;

    #pragma unroll
    for (int mi = 0; mi < 4; mi++)
        #pragma unroll
        for (int nt = 0; nt < 8; nt++) {
            int m = m0 + wm + 16 * mi + gq;
            int n = n0 + wn + 8 * nt + 2 * qi;
            int h = n >> 6, hd = n & 63, bb = m >> 11, s = m & (S_LEN - 1);
            float* p0 = dst + (((size_t)bb * NH + h) * S_LEN + s) * HDIM + hd;
            float* p1 = dst + (((size_t)bb * NH + h) * S_LEN + s + 8) * HDIM + hd;
            *(float2*)p0 = make_float2(u2f(f2tf(C[mi][nt][0] * scale)),
                                       u2f(f2tf(C[mi][nt][1] * scale)));
            *(float2*)p1 = make_float2(u2f(f2tf(C[mi][nt][2] * scale)),
                                       u2f(f2tf(C[mi][nt][3] * scale)));
        }
}

// ---------------------------------------------------------------------------
// Kernel 3: output projection + bias. grid=(4, 32)
// ---------------------------------------------------------------------------
__global__ __launch_bounds__(256, 1) void oproj_kernel(
    const float* __restrict__ bo, float* __restrict__ out)
{
    extern __shared__ float sm[];
    const int m0 = blockIdx.y * 128, n0 = blockIdx.x * 256;

    float C[4][8][4];
    gemm128_core(g_ctx + (size_t)m0 * D_DIM, g_woc + (size_t)n0 * D_DIM, C, sm);

    const int tid = threadIdx.x, wid = tid >> 5, lane = tid & 31;
    const int gq = lane >> 2, qi = lane & 3;
    const int wm = (wid >> 2) * 64, wn = (wid & 3) * 64;

    #pragma unroll
    for (int mi = 0; mi < 4; mi++)
        #pragma unroll
        for (int nt = 0; nt < 8; nt++) {
            int m = m0 + wm + 16 * mi + gq;
            int n = n0 + wn + 8 * nt + 2 * qi;
            float b0 = __ldg(bo + n), b1 = __ldg(bo + n + 1);
            *(float2*)(out + (size_t)m * D_DIM + n) =
                make_float2(C[mi][nt][0] + b0, C[mi][nt][1] + b1);
            *(float2*)(out + (size_t)(m + 8) * D_DIM + n) =
                make_float2(C[mi][nt][2] + b0, C[mi][nt][3] + b1);
        }
}

// ---------------------------------------------------------------------------
// Kernel 2: flash attention v3 — warp-exclusive softmax.
// 256 thr, 8 warps; warp owns 16 q-rows x all 128 keys. Q in registers.
// One __syncthreads per kt (K/V double-buffer). grid=(16, B*NH).
// ---------------------------------------------------------------------------
#define AV_OFF (2 * 8704)                       // after 2 K stages (floats)
#define ATTN_SMEM ((AV_OFF + 2 * 9216) * 4)     // 143360 B

__device__ __forceinline__ void attn_prefetch(
    uint32_t sbase, const float* __restrict__ kp, const float* __restrict__ vp, int kt)
{
    const int tid = threadIdx.x;
    const int st = kt & 1;
    #pragma unroll
    for (int t = 0; t < 8; t++) {
        int i = tid + t * 256, row = i >> 4, c4 = i & 15;
        cpa16(sbase + (st * 8704 + row * 68 + c4 * 4) * 4,
              kp + (size_t)(kt * 128 + row) * HDIM + c4 * 4);
    }
    #pragma unroll
    for (int t = 0; t < 8; t++) {
        int i = tid + t * 256, row = i >> 4, c4 = i & 15;
        cpa16(sbase + (AV_OFF + st * 9216 + row * 72 + c4 * 4) * 4,
              vp + (size_t)(kt * 128 + row) * HDIM + c4 * 4);
    }
    cpa_commit();
}

// C-fragment (exp'd scores, 16x8 tile) -> A-fragment for the PV mma.
__device__ __forceinline__ void p_to_afrag(const float c[4], uint32_t a[4], int lane) {
    const int qi = lane & 3;
    const int s0 = (lane & ~3) | (qi >> 1);
    const int s1 = s0 + 2;
    float t0 = __shfl_sync(0xffffffffu, c[0], s0);
    float t1 = __shfl_sync(0xffffffffu, c[1], s0);
    float t2 = __shfl_sync(0xffffffffu, c[2], s0);
    float t3 = __shfl_sync(0xffffffffu, c[3], s0);
    float u0 = __shfl_sync(0xffffffffu, c[0], s1);
    float u1 = __shfl_sync(0xffffffffu, c[1], s1);
    float u2 = __shfl_sync(0xffffffffu, c[2], s1);
    float u3 = __shfl_sync(0xffffffffu, c[3], s1);
    const bool odd = qi & 1;
    a[0] = f2tf(odd ? t1 : t0);
    a[1] = f2tf(odd ? t3 : t2);
    a[2] = f2tf(odd ? u1 : u0);
    a[3] = f2tf(odd ? u3 : u2);
}

__global__ __launch_bounds__(256, 1) void attn_kernel()
{
    extern __shared__ float sm[];
    const uint32_t sbase = smem_u32(sm);

    const int bh = blockIdx.y, qt = blockIdx.x;
    const int tid = threadIdx.x, wid = tid >> 5, lane = tid & 31;
    const int gq = lane >> 2, qi = lane & 3;
    const int wm = wid * 16;                 // warp's 16 q-rows

    const float* qp = g_q + ((size_t)bh * S_LEN + qt * 128) * HDIM;
    const float* kp = g_k + (size_t)bh * S_LEN * HDIM;
    const float* vp = g_v + (size_t)bh * S_LEN * HDIM;

    attn_prefetch(sbase, kp, vp, 0);

    // Q fragments in registers (Q is pre-scaled + tf32-rounded in gmem)
    uint32_t qa[8][4];
    {
        const float* r0 = qp + (size_t)(wm + gq) * HDIM;
        const float* r1 = qp + (size_t)(wm + 8 + gq) * HDIM;
        #pragma unroll
        for (int ks = 0; ks < 8; ks++) {
            qa[ks][0] = fbits(__ldg(r0 + 8 * ks + qi));
            qa[ks][1] = fbits(__ldg(r1 + 8 * ks + qi));
            qa[ks][2] = fbits(__ldg(r0 + 8 * ks + qi + 4));
            qa[ks][3] = fbits(__ldg(r1 + 8 * ks + qi + 4));
        }
    }

    float O[8][4];
    float m0 = -1e30f, m1 = -1e30f, l0 = 0.f, l1 = 0.f;
    #pragma unroll
    for (int nt = 0; nt < 8; nt++)
        #pragma unroll
        for (int r = 0; r < 4; r++) O[nt][r] = 0.f;

    #pragma unroll 1
    for (int kt = 0; kt < S_LEN / 128; kt++) {
        cpa_wait<0>();
        __syncthreads();                      // tile kt visible; buffer reuse safe
        if (kt + 1 < S_LEN / 128) attn_prefetch(sbase, kp, vp, kt + 1);

        const float* ks_ = sm + (kt & 1) * 8704;
        const float* vs_ = sm + AV_OFF + (kt & 1) * 9216;

        // S = Q @ K^T : 16 rows x 128 keys (16 n-tiles)
        float Cs[16][4];
        #pragma unroll
        for (int nt = 0; nt < 16; nt++)
            #pragma unroll
            for (int r = 0; r < 4; r++) Cs[nt][r] = 0.f;

        #pragma unroll
        for (int ksi = 0; ksi < 8; ksi++) {
            #pragma unroll
            for (int nt = 0; nt < 16; nt++) {
                const float* pb = ks_ + (8 * nt + gq) * 68 + 8 * ksi + qi;
                uint32_t b[2] = { fbits(pb[0]), fbits(pb[4]) };
                mma_tf32(Cs[nt], qa[ksi], b);
            }
        }

        // warp-local online softmax (rows wm+gq, wm+8+gq)
        float rm0 = Cs[0][0], rm1 = Cs[0][2];
        #pragma unroll
        for (int nt = 0; nt < 16; nt++) {
            rm0 = fmaxf(rm0, fmaxf(Cs[nt][0], Cs[nt][1]));
            rm1 = fmaxf(rm1, fmaxf(Cs[nt][2], Cs[nt][3]));
        }
        rm0 = fmaxf(rm0, __shfl_xor_sync(0xffffffffu, rm0, 1));
        rm0 = fmaxf(rm0, __shfl_xor_sync(0xffffffffu, rm0, 2));
        rm1 = fmaxf(rm1, __shfl_xor_sync(0xffffffffu, rm1, 1));
        rm1 = fmaxf(rm1, __shfl_xor_sync(0xffffffffu, rm1, 2));

        float mn0 = fmaxf(m0, rm0), mn1 = fmaxf(m1, rm1);
        float corr0 = __expf(m0 - mn0), corr1 = __expf(m1 - mn1);
        m0 = mn0; m1 = mn1;

        float ps0 = 0.f, ps1 = 0.f;
        #pragma unroll
        for (int nt = 0; nt < 16; nt++) {
            float e0 = __expf(Cs[nt][0] - mn0), e1 = __expf(Cs[nt][1] - mn0);
            float e2 = __expf(Cs[nt][2] - mn1), e3 = __expf(Cs[nt][3] - mn1);
            Cs[nt][0] = e0; Cs[nt][1] = e1; Cs[nt][2] = e2; Cs[nt][3] = e3;
            ps0 += e0 + e1; ps1 += e2 + e3;
        }
        ps0 += __shfl_xor_sync(0xffffffffu, ps0, 1);
        ps0 += __shfl_xor_sync(0xffffffffu, ps0, 2);
        ps1 += __shfl_xor_sync(0xffffffffu, ps1, 1);
        ps1 += __shfl_xor_sync(0xffffffffu, ps1, 2);
        l0 = l0 * corr0 + ps0;
        l1 = l1 * corr1 + ps1;

        #pragma unroll
        for (int nt = 0; nt < 8; nt++) {
            O[nt][0] *= corr0; O[nt][1] *= corr0;
            O[nt][2] *= corr1; O[nt][3] *= corr1;
        }

        // O += P @ V : 16 k-tiles over 128 keys, 8 n-tiles over hd=64
        #pragma unroll
        for (int kc = 0; kc < 16; kc++) {
            uint32_t a[4];
            p_to_afrag(Cs[kc], a, lane);
            const float* pv = vs_ + (size_t)(8 * kc + qi) * 72 + gq;
            #pragma unroll
            for (int nt = 0; nt < 8; nt++) {
                uint32_t b[2] = { fbits(pv[8 * nt]), fbits(pv[4 * 72 + 8 * nt]) };
                mma_tf32(O[nt], a, b);
            }
        }
    }

    // epilogue: normalize + write ctx [b,s,h,hd] (warp-exclusive rows)
    const int b_ = bh >> 4, h = bh & 15;
    const float inv0 = 1.f / l0, inv1 = 1.f / l1;
    const int s = qt * 128 + wm + gq;
    #pragma unroll
    for (int nt = 0; nt < 8; nt++) {
        int cc = 8 * nt + 2 * qi;
        float* p0 = g_ctx + (((size_t)b_ * S_LEN + s) * NH + h) * HDIM + cc;
        float* p1 = g_ctx + (((size_t)b_ * S_LEN + s + 8) * NH + h) * HDIM + cc;
        *(float2*)p0 = make_float2(u2f(f2tf(O[nt][0] * inv0)),
                                   u2f(f2tf(O[nt][1] * inv0)));
        *(float2*)p1 = make_float2(u2f(f2tf(O[nt][2] * inv1)),
                                   u2f(f2tf(O[nt][3] * inv1)));
    }
}

// ---------------------------------------------------------------------------
extern "C" void kernel_launch(void* const* d_in, const int* in_sizes, int n_in,
                              void* d_out, int out_size)
{
    const float* x  = (const float*)d_in[0];
    const float* wq = (const float*)d_in[1];
    const float* wk = (const float*)d_in[2];
    const float* wv = (const float*)d_in[3];
    const float* wo = (const float*)d_in[4];
    const float* bo = (const float*)d_in[5];
    float* out = (float*)d_out;

    cudaFuncSetAttribute(qkv_kernel,   cudaFuncAttributeMaxDynamicSharedMemorySize, GEMM_SMEM);
    cudaFuncSetAttribute(oproj_kernel, cudaFuncAttributeMaxDynamicSharedMemorySize, GEMM_SMEM);
    cudaFuncSetAttribute(attn_kernel,  cudaFuncAttributeMaxDynamicSharedMemorySize, ATTN_SMEM);

    prep_kernel<<<dim3(256, 5), 256>>>(x, wq, wk, wv, wo);
    qkv_kernel<<<dim3(D_DIM / 256, M_TOT / 128, 3), 256, GEMM_SMEM>>>();
    attn_kernel<<<dim3(S_LEN / 128, NB * NH), 256, ATTN_SMEM>>>();
    oproj_kernel<<<dim3(D_DIM / 256, M_TOT / 128), 256, GEMM_SMEM>>>(bo, out);
}